// round 12
// baseline (speedup 1.0000x reference)
#include <cuda_runtime.h>
#include <cuda_fp16.h>
#include <math.h>
#include <stdint.h>

// Problem constants
#define Nn 716
#define Tt 12
#define Cc 10
#define Bb 64
#define Ee 11441
#define KP 768                 // padded storage dim (multiple of 128)
#define NGRP 4                 // batch pipeline groups
#define GB (Bb / NGRP)         // 16 batches per group

// -------- device scratch (allocation-free rule; zero-initialized at load) ----
__device__ float g_lhs[Bb * Nn * Tt];
__device__ float g_rhs[Bb * Nn * Tt];
__device__ __half g_Ah[KP * KP];                 // Vs split hi  [n][m]
__device__ __half g_Al[KP * KP];                 // Vs split lo
__device__ __half g_Ph[(size_t)Bb * KP * KP];    // P split hi   [b][m][k]
__device__ __half g_Pl[(size_t)Bb * KP * KP];    // P split lo

extern __shared__ char dynsmem[];

__device__ __forceinline__ uint32_t smem_u32(const void* p) {
    uint32_t a;
    asm("{ .reg .u64 t; cvta.to.shared.u64 t, %1; cvt.u32.u64 %0, t; }" : "=r"(a) : "l"(p));
    return a;
}
__device__ __forceinline__ void cpa16(uint32_t dst, const void* src) {
    asm volatile("cp.async.cg.shared.global [%0], [%1], 16;" :: "r"(dst), "l"(src));
}
#define CP_COMMIT() asm volatile("cp.async.commit_group;" ::: "memory")
#define CP_WAIT1()  asm volatile("cp.async.wait_group 1;" ::: "memory")
#define CP_WAIT0()  asm volatile("cp.async.wait_group 0;" ::: "memory")

__device__ __forceinline__ void ldsm_x4(uint32_t addr, uint32_t* r) {
    asm volatile("ldmatrix.sync.aligned.m8n8.x4.shared.b16 {%0,%1,%2,%3}, [%4];"
        : "=r"(r[0]), "=r"(r[1]), "=r"(r[2]), "=r"(r[3]) : "r"(addr));
}
__device__ __forceinline__ void ldsm_x4t(uint32_t addr, uint32_t* r) {
    asm volatile("ldmatrix.sync.aligned.m8n8.x4.trans.shared.b16 {%0,%1,%2,%3}, [%4];"
        : "=r"(r[0]), "=r"(r[1]), "=r"(r[2]), "=r"(r[3]) : "r"(addr));
}
__device__ __forceinline__ void mma16816(float* c, const uint32_t* a, const uint32_t* b) {
    asm volatile("mma.sync.aligned.m16n8k16.row.col.f32.f16.f16.f32 "
        "{%0,%1,%2,%3}, {%4,%5,%6,%7}, {%8,%9}, {%0,%1,%2,%3};"
        : "+f"(c[0]), "+f"(c[1]), "+f"(c[2]), "+f"(c[3])
        : "r"(a[0]), "r"(a[1]), "r"(a[2]), "r"(a[3]), "r"(b[0]), "r"(b[1]));
}

// ---------------------------------------------------------------------------
// K0: merged prologue (ragged linear + Vs split), one launch.
// ---------------------------------------------------------------------------
#define NB_LHS  ((Bb * Nn + 7) / 8)          // 8 warps/block
#define NB_PREP ((KP * KP) / 256)
__global__ void __launch_bounds__(256) k_combo(
    const float* __restrict__ vals, const float* __restrict__ Wf,
    const float* __restrict__ bias, const float* __restrict__ W1,
    const float* __restrict__ W2,  const float* __restrict__ W3,
    const float* __restrict__ Vs) {
    if (blockIdx.x >= NB_LHS) {
        int idx = (blockIdx.x - NB_LHS) * 256 + threadIdx.x;
        int n = idx / KP, m = idx % KP;
        float v = (n < Nn && m < Nn) ? Vs[n * Nn + m] : 0.f;
        __half hi = __float2half_rn(v);
        __half lo = __float2half_rn(v - __half2float(hi));
        g_Ah[idx] = hi;
        g_Al[idx] = lo;
        return;
    }
    int gwarp = blockIdx.x * 8 + (threadIdx.x >> 5);
    int lane  = threadIdx.x & 31;
    if (gwarp >= Bb * Nn) return;
    int b = gwarp / Nn, n = gwarp % Nn;
    int r   = n % 17;
    int s   = 8 * n + (n / 17) * 136 + (r * (r - 1)) / 2;
    int deg = 8 + r;

    float w1[Tt], sumW1 = 0.f;
#pragma unroll
    for (int t = 0; t < Tt; t++) { w1[t] = W1[t]; sumW1 += w1[t]; }
    float rhp[Tt], lhp[Cc];
#pragma unroll
    for (int t = 0; t < Tt; t++) rhp[t] = 0.f;
#pragma unroll
    for (int c = 0; c < Cc; c++) lhp[c] = 0.f;

    if (lane < deg) {
        int e = s + lane;
        float v[Tt], a = 0.f, wf = 0.f;
#pragma unroll
        for (int t = 0; t < Tt; t++) {
            v[t] = vals[(b * Tt + t) * Ee + e];
            a += v[t] * w1[t];
        }
#pragma unroll
        for (int c = 0; c < Cc; c++) {
            float wc = Wf[c * Ee + e];
            lhp[c] = a * wc;
            wf += W3[c] * wc;
        }
#pragma unroll
        for (int t = 0; t < Tt; t++) rhp[t] = v[t] * wf;
    }
#pragma unroll
    for (int o = 16; o > 0; o >>= 1) {
#pragma unroll
        for (int t = 0; t < Tt; t++) rhp[t] += __shfl_xor_sync(0xffffffffu, rhp[t], o);
#pragma unroll
        for (int c = 0; c < Cc; c++) lhp[c] += __shfl_xor_sync(0xffffffffu, lhp[c], o);
    }
    if (lane < Tt) {
        int t = lane;
        float bias3 = 0.f, l = 0.f;
#pragma unroll
        for (int c = 0; c < Cc; c++) {
            float bc = bias[n * Cc + c];
            bias3 += W3[c] * bc;
            l += (lhp[c] + bc * sumW1) * W2[c * Tt + t];
        }
        g_rhs[(b * Nn + n) * Tt + t] = rhp[t] + bias3;
        g_lhs[(b * Nn + n) * Tt + t] = l;
    }
}

// ---------------------------------------------------------------------------
// K2: sigmoid panel P[b][m][k] -> fp16 split. One warp per m-row.
// ---------------------------------------------------------------------------
__global__ void __launch_bounds__(512) k_pgen(const float* __restrict__ bs, int b0) {
    __shared__ float rhs_s[Nn * 13];    // stride 13: conflict-free
    int b = blockIdx.y + b0, m0 = blockIdx.x * 16;
    int tid = threadIdx.x, lane = tid & 31, w = tid >> 5;

    for (int i = tid; i < Nn * Tt; i += 512) {
        int k = i / Tt, t = i - k * Tt;
        rhs_s[k * 13 + t] = g_rhs[(b * Nn + k) * Tt + t];
    }
    __syncthreads();

    int m = m0 + w;
    if (m >= Nn) return;
    size_t rowoff = ((size_t)b * KP + m) * KP;
    float l[Tt];
    {
        const float4* lp = (const float4*)(g_lhs + (b * Nn + m) * Tt);
        float4 x0 = lp[0], x1 = lp[1], x2 = lp[2];
        l[0]=x0.x; l[1]=x0.y; l[2]=x0.z; l[3]=x0.w;
        l[4]=x1.x; l[5]=x1.y; l[6]=x1.z; l[7]=x1.w;
        l[8]=x2.x; l[9]=x2.y; l[10]=x2.z; l[11]=x2.w;
    }
    const float* bsrow = bs + m * Nn;
    for (int k = lane * 2; k < Nn; k += 64) {
        float x0 = bsrow[k], x1 = bsrow[k + 1];
#pragma unroll
        for (int t = 0; t < Tt; t++) {
            x0 += l[t] * rhs_s[k * 13 + t];
            x1 += l[t] * rhs_s[(k + 1) * 13 + t];
        }
        float p0 = 1.f / (1.f + __expf(-x0));
        float p1 = 1.f / (1.f + __expf(-x1));
        __half h0 = __float2half_rn(p0);
        __half h1 = __float2half_rn(p1);
        __half q0 = __float2half_rn(p0 - __half2float(h0));
        __half q1 = __float2half_rn(p1 - __half2float(h1));
        *(__half2*)(g_Ph + rowoff + k) = __halves2half2(h0, h1);
        *(__half2*)(g_Pl + rowoff + k) = __halves2half2(q0, q1);
    }
}

// ---------------------------------------------------------------------------
// K3: mma.sync fp16 GEMM, error-split (R8-validated body).
// ---------------------------------------------------------------------------
#define A_SPL  10240
#define B_SPL  8704
#define O_AH   0
#define O_AL   A_SPL
#define O_BH   (2 * A_SPL)
#define O_BL   (2 * A_SPL + B_SPL)
#define STG_B  (2 * A_SPL + 2 * B_SPL)   // 37888
#define NSTG   3
#define SMEM_MMA (NSTG * STG_B)          // 113664
#define NCH    23

__global__ void __launch_bounds__(256, 2) k_mma(float* __restrict__ out, int b0) {
    uint32_t sb = smem_u32(dynsmem);
    int tid = threadIdx.x, lane = tid & 31, wid = tid >> 5;
    int wm = wid >> 2, wn = wid & 3;
    int b = blockIdx.y + b0, mt = blockIdx.x / 6, nt = blockIdx.x % 6;

    int ar0 = tid >> 2,         ak0 = (tid & 3) * 8;
    int ar1 = (tid + 256) >> 2;
    int br0 = tid >> 4,         bn0 = (tid & 15) * 8;
    int br1 = (tid + 256) >> 4;

    const size_t aRowBase = (size_t)(mt * 128) * KP;
    const size_t bBase    = (size_t)b * KP * KP + nt * 128;

    const uint32_t aoff = ((wm * 64 + (lane & 15)) * 40 + (lane >> 4) * 8) * 2;
    const uint32_t boff = (((lane & 15)) * 136 + wn * 32 + (lane >> 4) * 8) * 2;

    float acc[4][4][4];
#pragma unroll
    for (int i = 0; i < 4; i++)
#pragma unroll
        for (int j = 0; j < 4; j++)
#pragma unroll
            for (int q = 0; q < 4; q++) acc[i][j][q] = 0.f;

    auto issue = [&](int c, int slot) {
        int k0 = c * 32;
        const __half* gAh = g_Ah + aRowBase + k0;
        const __half* gAl = g_Al + aRowBase + k0;
        const __half* gBh = g_Ph + bBase + (size_t)k0 * KP;
        const __half* gBl = g_Pl + bBase + (size_t)k0 * KP;
        uint32_t st = sb + slot * STG_B;
        cpa16(st + O_AH + ar0 * 80 + ak0 * 2, gAh + (size_t)ar0 * KP + ak0);
        cpa16(st + O_AH + ar1 * 80 + ak0 * 2, gAh + (size_t)ar1 * KP + ak0);
        cpa16(st + O_AL + ar0 * 80 + ak0 * 2, gAl + (size_t)ar0 * KP + ak0);
        cpa16(st + O_AL + ar1 * 80 + ak0 * 2, gAl + (size_t)ar1 * KP + ak0);
        cpa16(st + O_BH + br0 * 272 + bn0 * 2, gBh + (size_t)br0 * KP + bn0);
        cpa16(st + O_BH + br1 * 272 + bn0 * 2, gBh + (size_t)br1 * KP + bn0);
        cpa16(st + O_BL + br0 * 272 + bn0 * 2, gBl + (size_t)br0 * KP + bn0);
        cpa16(st + O_BL + br1 * 272 + bn0 * 2, gBl + (size_t)br1 * KP + bn0);
    };

    issue(0, 0); CP_COMMIT();
    issue(1, 1); CP_COMMIT();

    int slot = 0, slot2 = 2;
    for (int i = 0; i < NCH; i++) {
        if (i + 1 < NCH) CP_WAIT1(); else CP_WAIT0();
        __syncthreads();
        if (i + 2 < NCH) { issue(i + 2, slot2); CP_COMMIT(); }

        uint32_t st = sb + slot * STG_B;
#pragma unroll
        for (int kk = 0; kk < 2; kk++) {
            const uint32_t kA = st + aoff + kk * 32;
            const uint32_t kB = st + boff + kk * 16 * 272;

            uint32_t bh[4][2], bl[4][2];
#pragma unroll
            for (int nh = 0; nh < 2; nh++) {
                uint32_t t[4];
                ldsm_x4t(kB + O_BH + nh * 32, t);
                bh[nh * 2][0] = t[0]; bh[nh * 2][1] = t[1];
                bh[nh * 2 + 1][0] = t[2]; bh[nh * 2 + 1][1] = t[3];
            }
#pragma unroll
            for (int nh = 0; nh < 2; nh++) {
                uint32_t t[4];
                ldsm_x4t(kB + O_BL + nh * 32, t);
                bl[nh * 2][0] = t[0]; bl[nh * 2][1] = t[1];
                bl[nh * 2 + 1][0] = t[2]; bl[nh * 2 + 1][1] = t[3];
            }
            uint32_t ah[4][4];
#pragma unroll
            for (int mf = 0; mf < 4; mf++)
                ldsm_x4(kA + O_AH + mf * 16 * 80, ah[mf]);

#pragma unroll
            for (int mf = 0; mf < 4; mf++)
#pragma unroll
                for (int nf = 0; nf < 4; nf++)
                    mma16816(acc[mf][nf], ah[mf], bh[nf]);
#pragma unroll
            for (int mf = 0; mf < 4; mf++)
#pragma unroll
                for (int nf = 0; nf < 4; nf++)
                    mma16816(acc[mf][nf], ah[mf], bl[nf]);

#pragma unroll
            for (int mf = 0; mf < 4; mf++) {
                uint32_t al[4];
                ldsm_x4(kA + O_AL + mf * 16 * 80, al);
#pragma unroll
                for (int nf = 0; nf < 4; nf++)
                    mma16816(acc[mf][nf], al, bh[nf]);
            }
        }
        slot = (slot == 2) ? 0 : slot + 1;
        slot2 = (slot2 == 2) ? 0 : slot2 + 1;
    }

    int rbase = mt * 128 + wm * 64;
    int cbase = nt * 128 + wn * 32;
#pragma unroll
    for (int mf = 0; mf < 4; mf++) {
#pragma unroll
        for (int nf = 0; nf < 4; nf++) {
            int r = rbase + mf * 16 + (lane >> 2);
            int c = cbase + nf * 8 + (lane & 3) * 2;
            if (c < Nn) {
                if (r < Nn)
                    *(float2*)(out + ((size_t)b * Nn + r) * Nn + c) =
                        make_float2(acc[mf][nf][0], acc[mf][nf][1]);
                if (r + 8 < Nn)
                    *(float2*)(out + ((size_t)b * Nn + r + 8) * Nn + c) =
                        make_float2(acc[mf][nf][2], acc[mf][nf][3]);
            }
        }
    }
}

// ---------------------------------------------------------------------------
// K4: in-place column softmax, online form (R11-validated).
// ---------------------------------------------------------------------------
#define SCOL 16
#define SMX_SMEM ((Nn * 17 + 16 * SCOL * 2 + SCOL * 2) * 4)
__global__ void __launch_bounds__(256) k_smax(float* __restrict__ out, int b0) {
    float* tile = (float*)dynsmem;               // [716][17]
    float* auxm = tile + Nn * 17;                // [16][16] partial max
    float* auxs = auxm + 16 * SCOL;              // [16][16] partial scaled sum
    float* colM = auxs + 16 * SCOL;              // [16]
    float* colS = colM + SCOL;                   // [16] (1/S)
    int b = blockIdx.y + b0, k0 = blockIdx.x * SCOL;
    int tid = threadIdx.x, c = tid & 15, g = tid >> 4;
    const size_t base = (size_t)b * Nn * Nn + k0;

    for (int i = tid; i < Nn * SCOL; i += 256) {
        int row = i >> 4, cc = i & 15;
        tile[row * 17 + cc] = (k0 + cc < Nn) ? out[base + (size_t)row * Nn + cc] : -1e30f;
    }
    __syncthreads();

    float m = -1e30f, s = 0.f;
    for (int row = g; row < Nn; row += 16) {
        float x = tile[row * 17 + c];
        if (x > m) { s = s * __expf(m - x) + 1.f; m = x; }
        else       { s += __expf(x - m); }
    }
    auxm[g * SCOL + c] = m;
    auxs[g * SCOL + c] = s;
    __syncthreads();

    if (tid < SCOL) {
        float M = -1e30f;
#pragma unroll
        for (int gg = 0; gg < 16; gg++) M = fmaxf(M, auxm[gg * SCOL + tid]);
        float S = 0.f;
#pragma unroll
        for (int gg = 0; gg < 16; gg++)
            S += auxs[gg * SCOL + tid] * __expf(auxm[gg * SCOL + tid] - M);
        colM[tid] = M;
        colS[tid] = 1.f / S;
    }
    __syncthreads();

    for (int i = tid; i < Nn * SCOL; i += 256) {
        int row = i >> 4, cc = i & 15;
        if (k0 + cc < Nn)
            out[base + (size_t)row * Nn + cc] =
                __expf(tile[row * 17 + cc] - colM[cc]) * colS[cc];
    }
}

// ---------------------------------------------------------------------------
// Streams/events created at module init (before harness mem checkpoint).
// ---------------------------------------------------------------------------
struct PipeRes {
    cudaStream_t sA, sB;
    cudaEvent_t e0, ep[NGRP], em[NGRP], es;
    PipeRes() {
        cudaStreamCreateWithFlags(&sA, cudaStreamNonBlocking);
        cudaStreamCreateWithFlags(&sB, cudaStreamNonBlocking);
        cudaEventCreateWithFlags(&e0, cudaEventDisableTiming);
        for (int g = 0; g < NGRP; g++) {
            cudaEventCreateWithFlags(&ep[g], cudaEventDisableTiming);
            cudaEventCreateWithFlags(&em[g], cudaEventDisableTiming);
        }
        cudaEventCreateWithFlags(&es, cudaEventDisableTiming);
    }
};
static PipeRes g_pr;

// ---------------------------------------------------------------------------
extern "C" void kernel_launch(void* const* d_in, const int* in_sizes, int n_in,
                              void* d_out, int out_size) {
    const float* vals = (const float*)d_in[0];
    const float* Wf   = (const float*)d_in[1];
    const float* bias = (const float*)d_in[2];
    const float* W1   = (const float*)d_in[3];
    const float* W2   = (const float*)d_in[4];
    const float* W3   = (const float*)d_in[5];
    const float* bs   = (const float*)d_in[6];
    const float* Vs   = (const float*)d_in[7];
    float* out = (float*)d_out;

    cudaFuncSetAttribute(k_mma,  cudaFuncAttributeMaxDynamicSharedMemorySize, SMEM_MMA);
    cudaFuncSetAttribute(k_smax, cudaFuncAttributeMaxDynamicSharedMemorySize, SMX_SMEM);

    cudaStream_t S = cudaStreamPerThread;   // the stream plain <<<>>> maps to here

    // prologue on S
    k_combo<<<NB_LHS + NB_PREP, 256, 0, S>>>(vals, Wf, bias, W1, W2, W3, Vs);
    cudaEventRecord(g_pr.e0, S);

    // stream A: all pgen groups, pipelined ahead
    cudaStreamWaitEvent(g_pr.sA, g_pr.e0, 0);
    for (int g = 0; g < NGRP; g++) {
        dim3 gp((Nn + 15) / 16, GB);
        k_pgen<<<gp, 512, 0, g_pr.sA>>>(bs, g * GB);
        cudaEventRecord(g_pr.ep[g], g_pr.sA);
    }

    // main stream: mma per group; stream B: smax per group
    for (int g = 0; g < NGRP; g++) {
        cudaStreamWaitEvent(S, g_pr.ep[g], 0);
        dim3 gm(36, GB);
        k_mma<<<gm, 256, SMEM_MMA, S>>>(out, g * GB);
        cudaEventRecord(g_pr.em[g], S);
        cudaStreamWaitEvent(g_pr.sB, g_pr.em[g], 0);
        dim3 gs((Nn + SCOL - 1) / SCOL, GB);
        k_smax<<<gs, 256, SMX_SMEM, g_pr.sB>>>(out, g * GB);
    }

    // join both side streams back into S
    cudaEventRecord(g_pr.es, g_pr.sB);
    cudaStreamWaitEvent(S, g_pr.es, 0);
}

// round 13
// speedup vs baseline: 1.0246x; 1.0246x over previous
#include <cuda_runtime.h>
#include <cuda_fp16.h>
#include <math.h>
#include <stdint.h>

// Problem constants
#define Nn 716
#define Tt 12
#define Cc 10
#define Bb 64
#define Ee 11441
#define KP 768                 // padded storage dim (multiple of 128)

// -------- device scratch (allocation-free rule; zero-initialized at load) ----
__device__ float g_lhs[Bb * Nn * Tt];
__device__ float g_rhs[Bb * Nn * Tt];
__device__ __half g_Ah[KP * KP];                 // Vs split hi  [n][m]
__device__ __half g_Al[KP * KP];                 // Vs split lo
__device__ __half g_Ph[(size_t)Bb * KP * KP];    // P split hi   [b][m][k]
__device__ __half g_Pl[(size_t)Bb * KP * KP];    // P split lo

extern __shared__ char dynsmem[];

__device__ __forceinline__ uint32_t smem_u32(const void* p) {
    uint32_t a;
    asm("{ .reg .u64 t; cvta.to.shared.u64 t, %1; cvt.u32.u64 %0, t; }" : "=r"(a) : "l"(p));
    return a;
}
__device__ __forceinline__ void cpa16(uint32_t dst, const void* src) {
    asm volatile("cp.async.cg.shared.global [%0], [%1], 16;" :: "r"(dst), "l"(src));
}
#define CP_COMMIT() asm volatile("cp.async.commit_group;" ::: "memory")
#define CP_WAIT1()  asm volatile("cp.async.wait_group 1;" ::: "memory")
#define CP_WAIT0()  asm volatile("cp.async.wait_group 0;" ::: "memory")

__device__ __forceinline__ void ldsm_x4(uint32_t addr, uint32_t* r) {
    asm volatile("ldmatrix.sync.aligned.m8n8.x4.shared.b16 {%0,%1,%2,%3}, [%4];"
        : "=r"(r[0]), "=r"(r[1]), "=r"(r[2]), "=r"(r[3]) : "r"(addr));
}
__device__ __forceinline__ void ldsm_x4t(uint32_t addr, uint32_t* r) {
    asm volatile("ldmatrix.sync.aligned.m8n8.x4.trans.shared.b16 {%0,%1,%2,%3}, [%4];"
        : "=r"(r[0]), "=r"(r[1]), "=r"(r[2]), "=r"(r[3]) : "r"(addr));
}
__device__ __forceinline__ void mma16816(float* c, const uint32_t* a, const uint32_t* b) {
    asm volatile("mma.sync.aligned.m16n8k16.row.col.f32.f16.f16.f32 "
        "{%0,%1,%2,%3}, {%4,%5,%6,%7}, {%8,%9}, {%0,%1,%2,%3};"
        : "+f"(c[0]), "+f"(c[1]), "+f"(c[2]), "+f"(c[3])
        : "r"(a[0]), "r"(a[1]), "r"(a[2]), "r"(a[3]), "r"(b[0]), "r"(b[1]));
}

// ---------------------------------------------------------------------------
// K0: merged prologue (ragged linear + Vs split), one launch.
// ---------------------------------------------------------------------------
#define NB_LHS  ((Bb * Nn + 7) / 8)          // 8 warps/block
#define NB_PREP ((KP * KP) / 256)
__global__ void __launch_bounds__(256) k_combo(
    const float* __restrict__ vals, const float* __restrict__ Wf,
    const float* __restrict__ bias, const float* __restrict__ W1,
    const float* __restrict__ W2,  const float* __restrict__ W3,
    const float* __restrict__ Vs) {
    if (blockIdx.x >= NB_LHS) {
        int idx = (blockIdx.x - NB_LHS) * 256 + threadIdx.x;
        int n = idx / KP, m = idx % KP;
        float v = (n < Nn && m < Nn) ? Vs[n * Nn + m] : 0.f;
        __half hi = __float2half_rn(v);
        __half lo = __float2half_rn(v - __half2float(hi));
        g_Ah[idx] = hi;
        g_Al[idx] = lo;
        return;
    }
    int gwarp = blockIdx.x * 8 + (threadIdx.x >> 5);
    int lane  = threadIdx.x & 31;
    if (gwarp >= Bb * Nn) return;
    int b = gwarp / Nn, n = gwarp % Nn;
    int r   = n % 17;
    int s   = 8 * n + (n / 17) * 136 + (r * (r - 1)) / 2;
    int deg = 8 + r;

    float w1[Tt], sumW1 = 0.f;
#pragma unroll
    for (int t = 0; t < Tt; t++) { w1[t] = W1[t]; sumW1 += w1[t]; }
    float rhp[Tt], lhp[Cc];
#pragma unroll
    for (int t = 0; t < Tt; t++) rhp[t] = 0.f;
#pragma unroll
    for (int c = 0; c < Cc; c++) lhp[c] = 0.f;

    if (lane < deg) {
        int e = s + lane;
        float v[Tt], a = 0.f, wf = 0.f;
#pragma unroll
        for (int t = 0; t < Tt; t++) {
            v[t] = vals[(b * Tt + t) * Ee + e];
            a += v[t] * w1[t];
        }
#pragma unroll
        for (int c = 0; c < Cc; c++) {
            float wc = Wf[c * Ee + e];
            lhp[c] = a * wc;
            wf += W3[c] * wc;
        }
#pragma unroll
        for (int t = 0; t < Tt; t++) rhp[t] = v[t] * wf;
    }
#pragma unroll
    for (int o = 16; o > 0; o >>= 1) {
#pragma unroll
        for (int t = 0; t < Tt; t++) rhp[t] += __shfl_xor_sync(0xffffffffu, rhp[t], o);
#pragma unroll
        for (int c = 0; c < Cc; c++) lhp[c] += __shfl_xor_sync(0xffffffffu, lhp[c], o);
    }
    if (lane < Tt) {
        int t = lane;
        float bias3 = 0.f, l = 0.f;
#pragma unroll
        for (int c = 0; c < Cc; c++) {
            float bc = bias[n * Cc + c];
            bias3 += W3[c] * bc;
            l += (lhp[c] + bc * sumW1) * W2[c * Tt + t];
        }
        g_rhs[(b * Nn + n) * Tt + t] = rhp[t] + bias3;
        g_lhs[(b * Nn + n) * Tt + t] = l;
    }
}

// ---------------------------------------------------------------------------
// K2: sigmoid panel P[b][m][k] -> fp16 split. One warp per m-row.
// rhs staged as [k][3] float4 (48B stride): 6 LDS.128 per k-pair (was 24 LDS.32).
// ---------------------------------------------------------------------------
__global__ void __launch_bounds__(512) k_pgen(const float* __restrict__ bs) {
    __shared__ float4 rhs_s[Nn * 3];    // [k][3] = 12 floats per k
    int b = blockIdx.y, m0 = blockIdx.x * 16;
    int tid = threadIdx.x, lane = tid & 31, w = tid >> 5;

    for (int i = tid; i < Nn * 3; i += 512) {
        int k = i / 3, q = i - k * 3;
        rhs_s[i] = *(const float4*)(g_rhs + ((size_t)b * Nn + k) * Tt + q * 4);
    }
    __syncthreads();

    int m = m0 + w;
    if (m >= Nn) return;
    size_t rowoff = ((size_t)b * KP + m) * KP;
    float l[Tt];
    {
        const float4* lp = (const float4*)(g_lhs + (b * Nn + m) * Tt);
        float4 x0 = lp[0], x1 = lp[1], x2 = lp[2];
        l[0]=x0.x; l[1]=x0.y; l[2]=x0.z; l[3]=x0.w;
        l[4]=x1.x; l[5]=x1.y; l[6]=x1.z; l[7]=x1.w;
        l[8]=x2.x; l[9]=x2.y; l[10]=x2.z; l[11]=x2.w;
    }
    const float* bsrow = bs + m * Nn;
    for (int k = lane * 2; k < Nn; k += 64) {     // Nn even: k+1 valid
        float2 bv = *(const float2*)(bsrow + k);
        float4 r0 = rhs_s[k * 3],       r1 = rhs_s[k * 3 + 1],       r2 = rhs_s[k * 3 + 2];
        float4 s0 = rhs_s[(k + 1) * 3], s1 = rhs_s[(k + 1) * 3 + 1], s2 = rhs_s[(k + 1) * 3 + 2];
        float x0 = bv.x, x1 = bv.y;
        x0 += l[0]*r0.x + l[1]*r0.y + l[2]*r0.z  + l[3]*r0.w;
        x0 += l[4]*r1.x + l[5]*r1.y + l[6]*r1.z  + l[7]*r1.w;
        x0 += l[8]*r2.x + l[9]*r2.y + l[10]*r2.z + l[11]*r2.w;
        x1 += l[0]*s0.x + l[1]*s0.y + l[2]*s0.z  + l[3]*s0.w;
        x1 += l[4]*s1.x + l[5]*s1.y + l[6]*s1.z  + l[7]*s1.w;
        x1 += l[8]*s2.x + l[9]*s2.y + l[10]*s2.z + l[11]*s2.w;
        float p0 = 1.f / (1.f + __expf(-x0));
        float p1 = 1.f / (1.f + __expf(-x1));
        __half h0 = __float2half_rn(p0);
        __half h1 = __float2half_rn(p1);
        __half q0 = __float2half_rn(p0 - __half2float(h0));
        __half q1 = __float2half_rn(p1 - __half2float(h1));
        *(__half2*)(g_Ph + rowoff + k) = __halves2half2(h0, h1);
        *(__half2*)(g_Pl + rowoff + k) = __halves2half2(q0, q1);
    }
}

// ---------------------------------------------------------------------------
// K3: mma.sync fp16 GEMM, error-split (R8-validated body).
// ---------------------------------------------------------------------------
#define A_SPL  10240
#define B_SPL  8704
#define O_AH   0
#define O_AL   A_SPL
#define O_BH   (2 * A_SPL)
#define O_BL   (2 * A_SPL + B_SPL)
#define STG_B  (2 * A_SPL + 2 * B_SPL)   // 37888
#define NSTG   3
#define SMEM_MMA (NSTG * STG_B)          // 113664
#define NCH    23

__global__ void __launch_bounds__(256, 2) k_mma(float* __restrict__ out) {
    uint32_t sb = smem_u32(dynsmem);
    int tid = threadIdx.x, lane = tid & 31, wid = tid >> 5;
    int wm = wid >> 2, wn = wid & 3;
    int b = blockIdx.y, mt = blockIdx.x / 6, nt = blockIdx.x % 6;

    int ar0 = tid >> 2,         ak0 = (tid & 3) * 8;
    int ar1 = (tid + 256) >> 2;
    int br0 = tid >> 4,         bn0 = (tid & 15) * 8;
    int br1 = (tid + 256) >> 4;

    const size_t aRowBase = (size_t)(mt * 128) * KP;
    const size_t bBase    = (size_t)b * KP * KP + nt * 128;

    const uint32_t aoff = ((wm * 64 + (lane & 15)) * 40 + (lane >> 4) * 8) * 2;
    const uint32_t boff = (((lane & 15)) * 136 + wn * 32 + (lane >> 4) * 8) * 2;

    float acc[4][4][4];
#pragma unroll
    for (int i = 0; i < 4; i++)
#pragma unroll
        for (int j = 0; j < 4; j++)
#pragma unroll
            for (int q = 0; q < 4; q++) acc[i][j][q] = 0.f;

    auto issue = [&](int c, int slot) {
        int k0 = c * 32;
        const __half* gAh = g_Ah + aRowBase + k0;
        const __half* gAl = g_Al + aRowBase + k0;
        const __half* gBh = g_Ph + bBase + (size_t)k0 * KP;
        const __half* gBl = g_Pl + bBase + (size_t)k0 * KP;
        uint32_t st = sb + slot * STG_B;
        cpa16(st + O_AH + ar0 * 80 + ak0 * 2, gAh + (size_t)ar0 * KP + ak0);
        cpa16(st + O_AH + ar1 * 80 + ak0 * 2, gAh + (size_t)ar1 * KP + ak0);
        cpa16(st + O_AL + ar0 * 80 + ak0 * 2, gAl + (size_t)ar0 * KP + ak0);
        cpa16(st + O_AL + ar1 * 80 + ak0 * 2, gAl + (size_t)ar1 * KP + ak0);
        cpa16(st + O_BH + br0 * 272 + bn0 * 2, gBh + (size_t)br0 * KP + bn0);
        cpa16(st + O_BH + br1 * 272 + bn0 * 2, gBh + (size_t)br1 * KP + bn0);
        cpa16(st + O_BL + br0 * 272 + bn0 * 2, gBl + (size_t)br0 * KP + bn0);
        cpa16(st + O_BL + br1 * 272 + bn0 * 2, gBl + (size_t)br1 * KP + bn0);
    };

    issue(0, 0); CP_COMMIT();
    issue(1, 1); CP_COMMIT();

    int slot = 0, slot2 = 2;
    for (int i = 0; i < NCH; i++) {
        if (i + 1 < NCH) CP_WAIT1(); else CP_WAIT0();
        __syncthreads();
        if (i + 2 < NCH) { issue(i + 2, slot2); CP_COMMIT(); }

        uint32_t st = sb + slot * STG_B;
#pragma unroll
        for (int kk = 0; kk < 2; kk++) {
            const uint32_t kA = st + aoff + kk * 32;
            const uint32_t kB = st + boff + kk * 16 * 272;

            uint32_t bh[4][2], bl[4][2];
#pragma unroll
            for (int nh = 0; nh < 2; nh++) {
                uint32_t t[4];
                ldsm_x4t(kB + O_BH + nh * 32, t);
                bh[nh * 2][0] = t[0]; bh[nh * 2][1] = t[1];
                bh[nh * 2 + 1][0] = t[2]; bh[nh * 2 + 1][1] = t[3];
            }
#pragma unroll
            for (int nh = 0; nh < 2; nh++) {
                uint32_t t[4];
                ldsm_x4t(kB + O_BL + nh * 32, t);
                bl[nh * 2][0] = t[0]; bl[nh * 2][1] = t[1];
                bl[nh * 2 + 1][0] = t[2]; bl[nh * 2 + 1][1] = t[3];
            }
            uint32_t ah[4][4];
#pragma unroll
            for (int mf = 0; mf < 4; mf++)
                ldsm_x4(kA + O_AH + mf * 16 * 80, ah[mf]);

#pragma unroll
            for (int mf = 0; mf < 4; mf++)
#pragma unroll
                for (int nf = 0; nf < 4; nf++)
                    mma16816(acc[mf][nf], ah[mf], bh[nf]);
#pragma unroll
            for (int mf = 0; mf < 4; mf++)
#pragma unroll
                for (int nf = 0; nf < 4; nf++)
                    mma16816(acc[mf][nf], ah[mf], bl[nf]);

#pragma unroll
            for (int mf = 0; mf < 4; mf++) {
                uint32_t al[4];
                ldsm_x4(kA + O_AL + mf * 16 * 80, al);
#pragma unroll
                for (int nf = 0; nf < 4; nf++)
                    mma16816(acc[mf][nf], al, bh[nf]);
            }
        }
        slot = (slot == 2) ? 0 : slot + 1;
        slot2 = (slot2 == 2) ? 0 : slot2 + 1;
    }

    int rbase = mt * 128 + wm * 64;
    int cbase = nt * 128 + wn * 32;
#pragma unroll
    for (int mf = 0; mf < 4; mf++) {
#pragma unroll
        for (int nf = 0; nf < 4; nf++) {
            int r = rbase + mf * 16 + (lane >> 2);
            int c = cbase + nf * 8 + (lane & 3) * 2;
            if (c < Nn) {
                if (r < Nn)
                    *(float2*)(out + ((size_t)b * Nn + r) * Nn + c) =
                        make_float2(acc[mf][nf][0], acc[mf][nf][1]);
                if (r + 8 < Nn)
                    *(float2*)(out + ((size_t)b * Nn + r + 8) * Nn + c) =
                        make_float2(acc[mf][nf][2], acc[mf][nf][3]);
            }
        }
    }
}

// ---------------------------------------------------------------------------
// K4: in-place column softmax, online form (R11-validated).
// ---------------------------------------------------------------------------
#define SCOL 16
#define SMX_SMEM ((Nn * 17 + 16 * SCOL * 2 + SCOL * 2) * 4)
__global__ void __launch_bounds__(256) k_smax(float* __restrict__ out) {
    float* tile = (float*)dynsmem;               // [716][17]
    float* auxm = tile + Nn * 17;                // [16][16] partial max
    float* auxs = auxm + 16 * SCOL;              // [16][16] partial scaled sum
    float* colM = auxs + 16 * SCOL;              // [16]
    float* colS = colM + SCOL;                   // [16] (1/S)
    int b = blockIdx.y, k0 = blockIdx.x * SCOL;
    int tid = threadIdx.x, c = tid & 15, g = tid >> 4;
    const size_t base = (size_t)b * Nn * Nn + k0;

    for (int i = tid; i < Nn * SCOL; i += 256) {
        int row = i >> 4, cc = i & 15;
        tile[row * 17 + cc] = (k0 + cc < Nn) ? out[base + (size_t)row * Nn + cc] : -1e30f;
    }
    __syncthreads();

    float m = -1e30f, s = 0.f;
    for (int row = g; row < Nn; row += 16) {
        float x = tile[row * 17 + c];
        if (x > m) { s = s * __expf(m - x) + 1.f; m = x; }
        else       { s += __expf(x - m); }
    }
    auxm[g * SCOL + c] = m;
    auxs[g * SCOL + c] = s;
    __syncthreads();

    if (tid < SCOL) {
        float M = -1e30f;
#pragma unroll
        for (int gg = 0; gg < 16; gg++) M = fmaxf(M, auxm[gg * SCOL + tid]);
        float S = 0.f;
#pragma unroll
        for (int gg = 0; gg < 16; gg++)
            S += auxs[gg * SCOL + tid] * __expf(auxm[gg * SCOL + tid] - M);
        colM[tid] = M;
        colS[tid] = 1.f / S;
    }
    __syncthreads();

    for (int i = tid; i < Nn * SCOL; i += 256) {
        int row = i >> 4, cc = i & 15;
        if (k0 + cc < Nn)
            out[base + (size_t)row * Nn + cc] =
                __expf(tile[row * 17 + cc] - colM[cc]) * colS[cc];
    }
}

// ---------------------------------------------------------------------------
extern "C" void kernel_launch(void* const* d_in, const int* in_sizes, int n_in,
                              void* d_out, int out_size) {
    const float* vals = (const float*)d_in[0];
    const float* Wf   = (const float*)d_in[1];
    const float* bias = (const float*)d_in[2];
    const float* W1   = (const float*)d_in[3];
    const float* W2   = (const float*)d_in[4];
    const float* W3   = (const float*)d_in[5];
    const float* bs   = (const float*)d_in[6];
    const float* Vs   = (const float*)d_in[7];
    float* out = (float*)d_out;

    cudaFuncSetAttribute(k_mma,  cudaFuncAttributeMaxDynamicSharedMemorySize, SMEM_MMA);
    cudaFuncSetAttribute(k_smax, cudaFuncAttributeMaxDynamicSharedMemorySize, SMX_SMEM);

    k_combo<<<NB_LHS + NB_PREP, 256>>>(vals, Wf, bias, W1, W2, W3, Vs);

    dim3 gp((Nn + 15) / 16, Bb);
    k_pgen<<<gp, 512>>>(bs);

    dim3 gm(36, Bb);                     // 6 M-tiles x 6 N-tiles
    k_mma<<<gm, 256, SMEM_MMA>>>(out);

    dim3 gs((Nn + SCOL - 1) / SCOL, Bb);
    k_smax<<<gs, 256, SMX_SMEM>>>(out);
}

// round 14
// speedup vs baseline: 1.0751x; 1.0493x over previous
#include <cuda_runtime.h>
#include <cuda_fp16.h>
#include <math.h>
#include <stdint.h>

// Problem constants
#define Nn 716
#define Tt 12
#define Cc 10
#define Bb 64
#define Ee 11441
#define KP 768                 // padded storage dim (multiple of 128)

// -------- device scratch (allocation-free rule; zero-initialized at load) ----
__device__ float g_lhs[Bb * Nn * Tt];
__device__ float g_rhs[Bb * Nn * Tt];
__device__ __half g_Ah[KP * KP];                 // Vs split hi  [n][m]
__device__ __half g_Al[KP * KP];                 // Vs split lo
__device__ __half g_Ph[(size_t)Bb * KP * KP];    // P split hi   [b][m][k]
__device__ __half g_Pl[(size_t)Bb * KP * KP];    // P split lo

extern __shared__ char dynsmem[];

__device__ __forceinline__ uint32_t smem_u32(const void* p) {
    uint32_t a;
    asm("{ .reg .u64 t; cvta.to.shared.u64 t, %1; cvt.u32.u64 %0, t; }" : "=r"(a) : "l"(p));
    return a;
}
__device__ __forceinline__ void cpa16(uint32_t dst, const void* src) {
    asm volatile("cp.async.cg.shared.global [%0], [%1], 16;" :: "r"(dst), "l"(src));
}
#define CP_COMMIT() asm volatile("cp.async.commit_group;" ::: "memory")
#define CP_WAIT1()  asm volatile("cp.async.wait_group 1;" ::: "memory")
#define CP_WAIT0()  asm volatile("cp.async.wait_group 0;" ::: "memory")

__device__ __forceinline__ void ldsm_x4(uint32_t addr, uint32_t* r) {
    asm volatile("ldmatrix.sync.aligned.m8n8.x4.shared.b16 {%0,%1,%2,%3}, [%4];"
        : "=r"(r[0]), "=r"(r[1]), "=r"(r[2]), "=r"(r[3]) : "r"(addr));
}
__device__ __forceinline__ void ldsm_x4t(uint32_t addr, uint32_t* r) {
    asm volatile("ldmatrix.sync.aligned.m8n8.x4.trans.shared.b16 {%0,%1,%2,%3}, [%4];"
        : "=r"(r[0]), "=r"(r[1]), "=r"(r[2]), "=r"(r[3]) : "r"(addr));
}
__device__ __forceinline__ void mma16816(float* c, const uint32_t* a, const uint32_t* b) {
    asm volatile("mma.sync.aligned.m16n8k16.row.col.f32.f16.f16.f32 "
        "{%0,%1,%2,%3}, {%4,%5,%6,%7}, {%8,%9}, {%0,%1,%2,%3};"
        : "+f"(c[0]), "+f"(c[1]), "+f"(c[2]), "+f"(c[3])
        : "r"(a[0]), "r"(a[1]), "r"(a[2]), "r"(a[3]), "r"(b[0]), "r"(b[1]));
}

// ---------------------------------------------------------------------------
// K0: merged prologue (ragged linear + Vs split), one launch.
// ---------------------------------------------------------------------------
#define NB_LHS  ((Bb * Nn + 7) / 8)          // 8 warps/block
#define NB_PREP ((KP * KP) / 256)
__global__ void __launch_bounds__(256) k_combo(
    const float* __restrict__ vals, const float* __restrict__ Wf,
    const float* __restrict__ bias, const float* __restrict__ W1,
    const float* __restrict__ W2,  const float* __restrict__ W3,
    const float* __restrict__ Vs) {
    if (blockIdx.x >= NB_LHS) {
        int idx = (blockIdx.x - NB_LHS) * 256 + threadIdx.x;
        int n = idx / KP, m = idx % KP;
        float v = (n < Nn && m < Nn) ? Vs[n * Nn + m] : 0.f;
        __half hi = __float2half_rn(v);
        __half lo = __float2half_rn(v - __half2float(hi));
        g_Ah[idx] = hi;
        g_Al[idx] = lo;
        return;
    }
    int gwarp = blockIdx.x * 8 + (threadIdx.x >> 5);
    int lane  = threadIdx.x & 31;
    if (gwarp >= Bb * Nn) return;
    int b = gwarp / Nn, n = gwarp % Nn;
    int r   = n % 17;
    int s   = 8 * n + (n / 17) * 136 + (r * (r - 1)) / 2;
    int deg = 8 + r;

    float w1[Tt], sumW1 = 0.f;
#pragma unroll
    for (int t = 0; t < Tt; t++) { w1[t] = W1[t]; sumW1 += w1[t]; }
    float rhp[Tt], lhp[Cc];
#pragma unroll
    for (int t = 0; t < Tt; t++) rhp[t] = 0.f;
#pragma unroll
    for (int c = 0; c < Cc; c++) lhp[c] = 0.f;

    if (lane < deg) {
        int e = s + lane;
        float v[Tt], a = 0.f, wf = 0.f;
#pragma unroll
        for (int t = 0; t < Tt; t++) {
            v[t] = vals[(b * Tt + t) * Ee + e];
            a += v[t] * w1[t];
        }
#pragma unroll
        for (int c = 0; c < Cc; c++) {
            float wc = Wf[c * Ee + e];
            lhp[c] = a * wc;
            wf += W3[c] * wc;
        }
#pragma unroll
        for (int t = 0; t < Tt; t++) rhp[t] = v[t] * wf;
    }
#pragma unroll
    for (int o = 16; o > 0; o >>= 1) {
#pragma unroll
        for (int t = 0; t < Tt; t++) rhp[t] += __shfl_xor_sync(0xffffffffu, rhp[t], o);
#pragma unroll
        for (int c = 0; c < Cc; c++) lhp[c] += __shfl_xor_sync(0xffffffffu, lhp[c], o);
    }
    if (lane < Tt) {
        int t = lane;
        float bias3 = 0.f, l = 0.f;
#pragma unroll
        for (int c = 0; c < Cc; c++) {
            float bc = bias[n * Cc + c];
            bias3 += W3[c] * bc;
            l += (lhp[c] + bc * sumW1) * W2[c * Tt + t];
        }
        g_rhs[(b * Nn + n) * Tt + t] = rhp[t] + bias3;
        g_lhs[(b * Nn + n) * Tt + t] = l;
    }
}

// ---------------------------------------------------------------------------
// K2: sigmoid panel P[b][m][k] -> fp16 split. One warp per m-row,
// rhs staged as [k][3] float4 (R13-validated).
// ---------------------------------------------------------------------------
__global__ void __launch_bounds__(512) k_pgen(const float* __restrict__ bs) {
    __shared__ float4 rhs_s[Nn * 3];    // [k][3] = 12 floats per k
    int b = blockIdx.y, m0 = blockIdx.x * 16;
    int tid = threadIdx.x, lane = tid & 31, w = tid >> 5;

    for (int i = tid; i < Nn * 3; i += 512) {
        int k = i / 3, q = i - k * 3;
        rhs_s[i] = *(const float4*)(g_rhs + ((size_t)b * Nn + k) * Tt + q * 4);
    }
    __syncthreads();

    int m = m0 + w;
    if (m >= Nn) return;
    size_t rowoff = ((size_t)b * KP + m) * KP;
    float l[Tt];
    {
        const float4* lp = (const float4*)(g_lhs + (b * Nn + m) * Tt);
        float4 x0 = lp[0], x1 = lp[1], x2 = lp[2];
        l[0]=x0.x; l[1]=x0.y; l[2]=x0.z; l[3]=x0.w;
        l[4]=x1.x; l[5]=x1.y; l[6]=x1.z; l[7]=x1.w;
        l[8]=x2.x; l[9]=x2.y; l[10]=x2.z; l[11]=x2.w;
    }
    const float* bsrow = bs + m * Nn;
    for (int k = lane * 2; k < Nn; k += 64) {     // Nn even: k+1 valid
        float2 bv = *(const float2*)(bsrow + k);
        float4 r0 = rhs_s[k * 3],       r1 = rhs_s[k * 3 + 1],       r2 = rhs_s[k * 3 + 2];
        float4 s0 = rhs_s[(k + 1) * 3], s1 = rhs_s[(k + 1) * 3 + 1], s2 = rhs_s[(k + 1) * 3 + 2];
        float x0 = bv.x, x1 = bv.y;
        x0 += l[0]*r0.x + l[1]*r0.y + l[2]*r0.z  + l[3]*r0.w;
        x0 += l[4]*r1.x + l[5]*r1.y + l[6]*r1.z  + l[7]*r1.w;
        x0 += l[8]*r2.x + l[9]*r2.y + l[10]*r2.z + l[11]*r2.w;
        x1 += l[0]*s0.x + l[1]*s0.y + l[2]*s0.z  + l[3]*s0.w;
        x1 += l[4]*s1.x + l[5]*s1.y + l[6]*s1.z  + l[7]*s1.w;
        x1 += l[8]*s2.x + l[9]*s2.y + l[10]*s2.z + l[11]*s2.w;
        float p0 = 1.f / (1.f + __expf(-x0));
        float p1 = 1.f / (1.f + __expf(-x1));
        __half h0 = __float2half_rn(p0);
        __half h1 = __float2half_rn(p1);
        __half q0 = __float2half_rn(p0 - __half2float(h0));
        __half q1 = __float2half_rn(p1 - __half2float(h1));
        *(__half2*)(g_Ph + rowoff + k) = __halves2half2(h0, h1);
        *(__half2*)(g_Pl + rowoff + k) = __halves2half2(q0, q1);
    }
}

// ---------------------------------------------------------------------------
// K3: mma.sync fp16 GEMM, error-split (R8-validated body).
// ---------------------------------------------------------------------------
#define A_SPL  10240
#define B_SPL  8704
#define O_AH   0
#define O_AL   A_SPL
#define O_BH   (2 * A_SPL)
#define O_BL   (2 * A_SPL + B_SPL)
#define STG_B  (2 * A_SPL + 2 * B_SPL)   // 37888
#define NSTG   3
#define SMEM_MMA (NSTG * STG_B)          // 113664
#define NCH    23

__global__ void __launch_bounds__(256, 2) k_mma(float* __restrict__ out) {
    uint32_t sb = smem_u32(dynsmem);
    int tid = threadIdx.x, lane = tid & 31, wid = tid >> 5;
    int wm = wid >> 2, wn = wid & 3;
    int b = blockIdx.y, mt = blockIdx.x / 6, nt = blockIdx.x % 6;

    int ar0 = tid >> 2,         ak0 = (tid & 3) * 8;
    int ar1 = (tid + 256) >> 2;
    int br0 = tid >> 4,         bn0 = (tid & 15) * 8;
    int br1 = (tid + 256) >> 4;

    const size_t aRowBase = (size_t)(mt * 128) * KP;
    const size_t bBase    = (size_t)b * KP * KP + nt * 128;

    const uint32_t aoff = ((wm * 64 + (lane & 15)) * 40 + (lane >> 4) * 8) * 2;
    const uint32_t boff = (((lane & 15)) * 136 + wn * 32 + (lane >> 4) * 8) * 2;

    float acc[4][4][4];
#pragma unroll
    for (int i = 0; i < 4; i++)
#pragma unroll
        for (int j = 0; j < 4; j++)
#pragma unroll
            for (int q = 0; q < 4; q++) acc[i][j][q] = 0.f;

    auto issue = [&](int c, int slot) {
        int k0 = c * 32;
        const __half* gAh = g_Ah + aRowBase + k0;
        const __half* gAl = g_Al + aRowBase + k0;
        const __half* gBh = g_Ph + bBase + (size_t)k0 * KP;
        const __half* gBl = g_Pl + bBase + (size_t)k0 * KP;
        uint32_t st = sb + slot * STG_B;
        cpa16(st + O_AH + ar0 * 80 + ak0 * 2, gAh + (size_t)ar0 * KP + ak0);
        cpa16(st + O_AH + ar1 * 80 + ak0 * 2, gAh + (size_t)ar1 * KP + ak0);
        cpa16(st + O_AL + ar0 * 80 + ak0 * 2, gAl + (size_t)ar0 * KP + ak0);
        cpa16(st + O_AL + ar1 * 80 + ak0 * 2, gAl + (size_t)ar1 * KP + ak0);
        cpa16(st + O_BH + br0 * 272 + bn0 * 2, gBh + (size_t)br0 * KP + bn0);
        cpa16(st + O_BH + br1 * 272 + bn0 * 2, gBh + (size_t)br1 * KP + bn0);
        cpa16(st + O_BL + br0 * 272 + bn0 * 2, gBl + (size_t)br0 * KP + bn0);
        cpa16(st + O_BL + br1 * 272 + bn0 * 2, gBl + (size_t)br1 * KP + bn0);
    };

    issue(0, 0); CP_COMMIT();
    issue(1, 1); CP_COMMIT();

    int slot = 0, slot2 = 2;
    for (int i = 0; i < NCH; i++) {
        if (i + 1 < NCH) CP_WAIT1(); else CP_WAIT0();
        __syncthreads();
        if (i + 2 < NCH) { issue(i + 2, slot2); CP_COMMIT(); }

        uint32_t st = sb + slot * STG_B;
#pragma unroll
        for (int kk = 0; kk < 2; kk++) {
            const uint32_t kA = st + aoff + kk * 32;
            const uint32_t kB = st + boff + kk * 16 * 272;

            uint32_t bh[4][2], bl[4][2];
#pragma unroll
            for (int nh = 0; nh < 2; nh++) {
                uint32_t t[4];
                ldsm_x4t(kB + O_BH + nh * 32, t);
                bh[nh * 2][0] = t[0]; bh[nh * 2][1] = t[1];
                bh[nh * 2 + 1][0] = t[2]; bh[nh * 2 + 1][1] = t[3];
            }
#pragma unroll
            for (int nh = 0; nh < 2; nh++) {
                uint32_t t[4];
                ldsm_x4t(kB + O_BL + nh * 32, t);
                bl[nh * 2][0] = t[0]; bl[nh * 2][1] = t[1];
                bl[nh * 2 + 1][0] = t[2]; bl[nh * 2 + 1][1] = t[3];
            }
            uint32_t ah[4][4];
#pragma unroll
            for (int mf = 0; mf < 4; mf++)
                ldsm_x4(kA + O_AH + mf * 16 * 80, ah[mf]);

#pragma unroll
            for (int mf = 0; mf < 4; mf++)
#pragma unroll
                for (int nf = 0; nf < 4; nf++)
                    mma16816(acc[mf][nf], ah[mf], bh[nf]);
#pragma unroll
            for (int mf = 0; mf < 4; mf++)
#pragma unroll
                for (int nf = 0; nf < 4; nf++)
                    mma16816(acc[mf][nf], ah[mf], bl[nf]);

#pragma unroll
            for (int mf = 0; mf < 4; mf++) {
                uint32_t al[4];
                ldsm_x4(kA + O_AL + mf * 16 * 80, al);
#pragma unroll
                for (int nf = 0; nf < 4; nf++)
                    mma16816(acc[mf][nf], al, bh[nf]);
            }
        }
        slot = (slot == 2) ? 0 : slot + 1;
        slot2 = (slot2 == 2) ? 0 : slot2 + 1;
    }

    int rbase = mt * 128 + wm * 64;
    int cbase = nt * 128 + wn * 32;
#pragma unroll
    for (int mf = 0; mf < 4; mf++) {
#pragma unroll
        for (int nf = 0; nf < 4; nf++) {
            int r = rbase + mf * 16 + (lane >> 2);
            int c = cbase + nf * 8 + (lane & 3) * 2;
            if (c < Nn) {
                if (r < Nn)
                    *(float2*)(out + ((size_t)b * Nn + r) * Nn + c) =
                        make_float2(acc[mf][nf][0], acc[mf][nf][1]);
                if (r + 8 < Nn)
                    *(float2*)(out + ((size_t)b * Nn + r + 8) * Nn + c) =
                        make_float2(acc[mf][nf][2], acc[mf][nf][3]);
            }
        }
    }
}

// ---------------------------------------------------------------------------
// K4: column softmax, REGISTER-RESIDENT: thread (g,c) owns rows g+32j of
// column k0+c (coalesced: warp = 2 rows x 16 consecutive cols). No data tile.
//   pass A: register max;  pass B: sum of independent exps;
//   smem combine of 32 partials/col;  pass C: normalize from regs + store.
// ---------------------------------------------------------------------------
#define SCOL 16
#define NROW 23      // ceil(716/32)
__global__ void __launch_bounds__(512) k_smax(float* __restrict__ out) {
    __shared__ float auxm[32 * SCOL], auxs[32 * SCOL], colM[SCOL], colS[SCOL];
    int b = blockIdx.y, k0 = blockIdx.x * SCOL;
    int tid = threadIdx.x, c = tid & 15, g = tid >> 4;   // g in 0..31
    int k = k0 + c;
    bool kok = k < Nn;
    float* colp = out + (size_t)b * Nn * Nn + k;

    float x[NROW];
    float m = -1e30f;
#pragma unroll
    for (int j = 0; j < NROW; j++) {
        int row = g + j * 32;
        x[j] = (kok && row < Nn) ? colp[(size_t)row * Nn] : -1e30f;
        m = fmaxf(m, x[j]);
    }
    float s = 0.f;
#pragma unroll
    for (int j = 0; j < NROW; j++) {
        int row = g + j * 32;
        if (row < Nn) s += __expf(x[j] - m);
    }
    auxm[g * SCOL + c] = m;
    auxs[g * SCOL + c] = s;
    __syncthreads();

    if (tid < SCOL) {
        float M = -1e30f;
#pragma unroll
        for (int gg = 0; gg < 32; gg++) M = fmaxf(M, auxm[gg * SCOL + tid]);
        float S = 0.f;
#pragma unroll
        for (int gg = 0; gg < 32; gg++)
            S += auxs[gg * SCOL + tid] * __expf(auxm[gg * SCOL + tid] - M);
        colM[tid] = M;
        colS[tid] = 1.f / S;
    }
    __syncthreads();

    float M = colM[c], iS = colS[c];
    if (kok) {
#pragma unroll
        for (int j = 0; j < NROW; j++) {
            int row = g + j * 32;
            if (row < Nn)
                colp[(size_t)row * Nn] = __expf(x[j] - M) * iS;
        }
    }
}

// ---------------------------------------------------------------------------
extern "C" void kernel_launch(void* const* d_in, const int* in_sizes, int n_in,
                              void* d_out, int out_size) {
    const float* vals = (const float*)d_in[0];
    const float* Wf   = (const float*)d_in[1];
    const float* bias = (const float*)d_in[2];
    const float* W1   = (const float*)d_in[3];
    const float* W2   = (const float*)d_in[4];
    const float* W3   = (const float*)d_in[5];
    const float* bs   = (const float*)d_in[6];
    const float* Vs   = (const float*)d_in[7];
    float* out = (float*)d_out;

    cudaFuncSetAttribute(k_mma, cudaFuncAttributeMaxDynamicSharedMemorySize, SMEM_MMA);

    k_combo<<<NB_LHS + NB_PREP, 256>>>(vals, Wf, bias, W1, W2, W3, Vs);

    dim3 gp((Nn + 15) / 16, Bb);
    k_pgen<<<gp, 512>>>(bs);

    dim3 gm(36, Bb);                     // 6 M-tiles x 6 N-tiles
    k_mma<<<gm, 256, SMEM_MMA>>>(out);

    dim3 gs((Nn + SCOL - 1) / SCOL, Bb);
    k_smax<<<gs, 512>>>(out);
}